// round 7
// baseline (speedup 1.0000x reference)
#include <cuda_runtime.h>
#include <cstdint>

#define B_  256
#define T_  2048
#define K2_ 52

// scratch (device globals: no allocations allowed)
__device__ float g_diff[B_];
__device__ int   g_done = 0;   // self-resetting completion ticket

#define FFMA2(d,a,b,c) asm("fma.rn.f32x2 %0, %1, %2, %3;" : "=l"(d) : "l"(a), "l"(b), "l"(c))
#define FADD2(d,a,b)   asm("add.rn.f32x2 %0, %1, %2;"     : "=l"(d) : "l"(a), "l"(b))

// ---------------------------------------------------------------------------
// Mega-kernel: one batch per 64-thread block.
//  1) int32/int64 detection for lengths/labels (block-local, deterministic)
//  2) forward recursion (proven R5 loop: thread s owns state s, M row in 26
//     packed f32x2 regs, shared ping-pong v, exact power-of-two renorm every
//     2nd step with zero-guard, x8-unrolled loop, static 8-slot emission ring)
//  3) gold score inline on the same 64 threads
//  4) last-done block reduces the mean deterministically
// ---------------------------------------------------------------------------
__global__ __launch_bounds__(64)
void crf_fwd_fused(const float* __restrict__ em,
                   const float* __restrict__ tr,
                   const void*  __restrict__ lens_raw,
                   const void*  __restrict__ labs_raw,
                   float* __restrict__ out)
{
    const int b = blockIdx.x;
    const int s = threadIdx.x;                  // 0..63
    const int srow = (s < K2_) ? s : (K2_ - 1); // clamp for idle lanes

    __shared__ __align__(16) float vb[2][64];
    __shared__ float red[64];
    __shared__ int   sOr;
    __shared__ int   sTicket;
    __shared__ float sFw;

    // ---- dtype detection: int64 lengths have all-zero odd 32-bit words ----
    if (s == 0) sOr = 0;
    __syncthreads();
    {
        const int* w = (const int*)lens_raw;
        int o = w[2 * s + 1] | w[2 * s + 129];  // odd words: 128 of them, 2/thread
        if (o) atomicOr(&sOr, 1);
    }
    __syncthreads();
    const bool is64 = (sOr == 0);
    const int len = is64 ? (int)(((const long long*)lens_raw)[b])
                         : ((const int*)lens_raw)[b];

    // ---- packed M row: m2[j] = (exp(tr[srow][2j]), exp(tr[srow][2j+1])) ----
    unsigned long long m2[26];
    {
        const float* row = tr + srow * K2_;
#pragma unroll
        for (int j = 0; j < 26; ++j) {
            float a = __expf(row[2 * j]);
            float c = __expf(row[2 * j + 1]);
            asm("mov.b64 %0, {%1, %2};" : "=l"(m2[j]) : "f"(a), "f"(c));
        }
    }

    // init p0 = one-hot on START tag (50)
    vb[0][s] = (s == 50) ? 1.0f : 0.0f;
    vb[1][s] = 0.0f;

    // emission prefetch ring (distance 8, static slots)
    const float* eb = em + ((size_t)b * T_) * K2_ + srow;
    float eraw[8];
#pragma unroll
    for (int i = 0; i < 8; ++i) {
        int idx = (i < len) ? i : (len - 1);
        eraw[i] = eb[(size_t)idx * K2_];
    }

    int lz = 0;      // sum of power-of-two exponents (exact)
    __syncthreads();

#define STEP(EI, SRC, DST, DOREN, TCUR) do {                                  \
    const float E_ = __expf(eraw[EI]);                                        \
    const ulonglong2* Vp_ = reinterpret_cast<const ulonglong2*>(vb[SRC]);     \
    ulonglong2 vv0_ = Vp_[0];                                                 \
    unsigned long long a0_=0ULL, a1_=0ULL, a2_=0ULL, a3_=0ULL;                \
    float scale_;                                                             \
    if (DOREN) {                                                              \
        unsigned bits_ = (unsigned)(vv0_.x & 0xffffffffULL);                  \
        int e_ = 0;                                                           \
        if (bits_) {                                                          \
            e_ = (int)((bits_ >> 23) & 0xff) - 127;                           \
            e_ = max(-126, min(126, e_));                                     \
        }                                                                     \
        lz += e_;                                                             \
        scale_ = __uint_as_float((unsigned)(127 - e_) << 23) * E_;            \
    } else {                                                                  \
        scale_ = E_;                                                          \
    }                                                                         \
    FFMA2(a0_, m2[0], vv0_.x, a0_);                                           \
    FFMA2(a1_, m2[1], vv0_.y, a1_);                                           \
    _Pragma("unroll")                                                         \
    for (int j_ = 1; j_ < 13; ++j_) {                                         \
        ulonglong2 vv_ = Vp_[j_];                                             \
        if (j_ & 1) { FFMA2(a2_, m2[2*j_], vv_.x, a2_);                       \
                      FFMA2(a3_, m2[2*j_+1], vv_.y, a3_); }                   \
        else        { FFMA2(a0_, m2[2*j_], vv_.x, a0_);                       \
                      FFMA2(a1_, m2[2*j_+1], vv_.y, a1_); }                   \
    }                                                                         \
    FADD2(a0_, a0_, a2_);                                                     \
    FADD2(a1_, a1_, a3_);                                                     \
    FADD2(a0_, a0_, a1_);                                                     \
    float qlo_ = __uint_as_float((unsigned)(a0_ & 0xffffffffULL));            \
    float qhi_ = __uint_as_float((unsigned)(a0_ >> 32));                      \
    if (s < K2_) vb[DST][s] = (qlo_ + qhi_) * scale_;                         \
    { int idx_ = (TCUR) + 8; idx_ = (idx_ > len - 1) ? (len - 1) : idx_;      \
      eraw[EI] = eb[(size_t)idx_ * K2_]; }                                    \
    __syncthreads();                                                          \
} while (0)

    int t = 0;
    const int nmain = len & ~7;
    for (; t < nmain; t += 8) {
        STEP(0, 0, 1, true,  t + 0);
        STEP(1, 1, 0, false, t + 1);
        STEP(2, 0, 1, true,  t + 2);
        STEP(3, 1, 0, false, t + 3);
        STEP(4, 0, 1, true,  t + 4);
        STEP(5, 1, 0, false, t + 5);
        STEP(6, 0, 1, true,  t + 6);
        STEP(7, 1, 0, false, t + 7);
    }
    // tail (0..7 steps), static ring slots since nmain % 8 == 0
    if (t < len) { STEP(0, 0, 1, true, t); ++t; }
    if (t < len) { STEP(1, 1, 0, true, t); ++t; }
    if (t < len) { STEP(2, 0, 1, true, t); ++t; }
    if (t < len) { STEP(3, 1, 0, true, t); ++t; }
    if (t < len) { STEP(4, 0, 1, true, t); ++t; }
    if (t < len) { STEP(5, 1, 0, true, t); ++t; }
    if (t < len) { STEP(6, 0, 1, true, t); ++t; }
#undef STEP

    // ---- terminal: fw = lz*ln2 + log( sum_s exp(trans[STOP][s]) * v[s] ) ----
    const float* vf = vb[len & 1];
    float term = 0.0f;
    if (s < K2_) term = __expf(tr[(K2_ - 1) * K2_ + s]) * vf[s];
    red[s] = term;
    __syncthreads();
    if (s == 0) {
        float acc = 0.0f;
        for (int i = 0; i < K2_; ++i) acc += red[i];
        sFw = (float)((double)lz * 0.69314718055994530942) + __logf(acc);
    }
    __syncthreads();

    // ---- gold score inline (same 64 threads) ----
    const long long* lb64 = ((const long long*)labs_raw) + (size_t)b * T_;
    const int*       lb32 = ((const int*)labs_raw) + (size_t)b * T_;
    float acc = 0.0f;
    for (int tt = s; tt < len; tt += 64) {
        int lab  = is64 ? (int)lb64[tt] : lb32[tt];
        acc += em[((size_t)b * T_ + tt) * K2_ + lab];
        int prev = (tt == 0) ? (K2_ - 2)
                             : (is64 ? (int)lb64[tt - 1] : lb32[tt - 1]);
        acc += tr[lab * K2_ + prev];
    }
    red[s] = acc;
    __syncthreads();
    for (int off = 32; off > 0; off >>= 1) {
        if (s < off) red[s] += red[s + off];
        __syncthreads();
    }
    if (s == 0) {
        int lastlab = is64 ? (int)lb64[len - 1] : lb32[len - 1];
        float gold = red[0] + tr[(K2_ - 1) * K2_ + lastlab];
        g_diff[b] = sFw - gold;
    }

    // ---- last-done block computes the deterministic mean ----
    __threadfence();
    __syncthreads();
    if (s == 0) sTicket = atomicAdd(&g_done, 1);
    __syncthreads();
    if (sTicket == B_ - 1) {
        __threadfence();
        float a = g_diff[s] + g_diff[s + 64] + g_diff[s + 128] + g_diff[s + 192];
        red[s] = a;
        __syncthreads();
        for (int off = 32; off > 0; off >>= 1) {
            if (s < off) red[s] += red[s + off];
            __syncthreads();
        }
        if (s == 0) {
            out[0] = red[0] * (1.0f / 256.0f);
            g_done = 0;   // reset for next graph replay
        }
    }
}

extern "C" void kernel_launch(void* const* d_in, const int* in_sizes, int n_in,
                              void* d_out, int out_size)
{
    const float* em   = (const float*)d_in[0];   // [B, T, K2] f32
    const float* tr   = (const float*)d_in[1];   // [K2, K2]   f32
    const void*  lens = d_in[2];                 // [B]    i32 or i64
    const void*  labs = d_in[3];                 // [B, T] i32 or i64

    crf_fwd_fused<<<B_, 64>>>(em, tr, lens, labs, (float*)d_out);
}

// round 8
// speedup vs baseline: 1.9128x; 1.9128x over previous
#include <cuda_runtime.h>
#include <cstdint>

#define B_  256
#define T_  2048
#define K2_ 52

// scratch (device globals: no allocations allowed)
__device__ float g_fw[B_];
__device__ float g_diff[B_];
__device__ int   g_len[B_];
__device__ int   g_ord[B_];
__device__ int   g_i64;    // 1 if lengths/labels buffers are int64, 0 if int32

#define FFMA2(d,a,b,c) asm("fma.rn.f32x2 %0, %1, %2, %3;" : "=l"(d) : "l"(a), "l"(b), "l"(c))
#define FADD2(d,a,b)   asm("add.rn.f32x2 %0, %1, %2;"     : "=l"(d) : "l"(a), "l"(b))

// ---------------------------------------------------------------------------
// Prep: detect int32 vs int64 for lengths (values in [1,2048], never 0).
// If int64 (LE), every odd 32-bit word is a zero high-half. Normalizes
// lengths into g_len and builds a longest-first permutation g_ord.
// ---------------------------------------------------------------------------
__global__ void prep_kernel(const void* __restrict__ lens_raw)
{
    __shared__ int orred;
    __shared__ int slen[B_];
    const int tid = threadIdx.x;   // 0..255
    if (tid == 0) orred = 0;
    __syncthreads();
    const int* w = (const int*)lens_raw;
    const int v = w[tid];
    if (tid & 1) atomicOr(&orred, v);
    __syncthreads();
    const int is64 = (orred == 0) ? 1 : 0;
    const int len = is64 ? (int)(((const long long*)lens_raw)[tid]) : v;
    g_len[tid] = len;
    slen[tid] = len;
    if (tid == 0) g_i64 = is64;
    __syncthreads();
    int rank = 0;
    for (int j = 0; j < B_; ++j) {
        int lj = slen[j];
        if (lj > len || (lj == len && j < tid)) ++rank;
    }
    g_ord[rank] = tid;
}

// ---------------------------------------------------------------------------
// Forward: grid=128 (one block per SM — no SM sharing), 128 threads/block.
// Sub-block 0 (warps 0,1 / SMSP 0,1) runs batch g_ord[bid] (long);
// sub-block 1 (warps 2,3 / SMSP 2,3) runs batch g_ord[255-bid] (short).
// Independent named barriers => the two recursions never wait on each other
// and never contend for issue slots. Loop body = proven R5 kernel:
// thread s owns state s, M row in 26 packed f32x2 regs, shared ping-pong v,
// exact power-of-two renorm every 2nd step with zero-guard, x8 unroll,
// static 8-slot emission prefetch ring.
// ---------------------------------------------------------------------------
__global__ __launch_bounds__(128)
void fwd_kernel(const float* __restrict__ em,
                const float* __restrict__ tr)
{
    const int tid  = threadIdx.x;               // 0..127
    const int half = tid >> 6;                  // sub-block 0/1
    const int s    = tid & 63;                  // state lane 0..63
    const int bar  = half + 1;                  // named barrier id 1/2
    const int b    = (half == 0) ? g_ord[blockIdx.x]
                                 : g_ord[(B_ - 1) - blockIdx.x];
    const int srow = (s < K2_) ? s : (K2_ - 1); // clamp for idle lanes
    const int len  = g_len[b];

    __shared__ __align__(16) float vb[2][2][64];   // [half][pingpong][64]
    __shared__ float red[2][64];

#define SUBBAR() asm volatile("bar.sync %0, 64;" :: "r"(bar) : "memory")

    // Packed M row: m2[j] = (exp(tr[srow][2j]), exp(tr[srow][2j+1]))
    unsigned long long m2[26];
    {
        const float* row = tr + srow * K2_;
#pragma unroll
        for (int j = 0; j < 26; ++j) {
            float a = __expf(row[2 * j]);
            float c = __expf(row[2 * j + 1]);
            asm("mov.b64 %0, {%1, %2};" : "=l"(m2[j]) : "f"(a), "f"(c));
        }
    }

    // init p0 = one-hot on START tag (50)
    vb[half][0][s] = (s == 50) ? 1.0f : 0.0f;
    vb[half][1][s] = 0.0f;

    // emission prefetch ring (distance 8, static slots)
    const float* eb = em + ((size_t)b * T_) * K2_ + srow;
    float eraw[8];
#pragma unroll
    for (int i = 0; i < 8; ++i) {
        int idx = (i < len) ? i : (len - 1);
        eraw[i] = eb[(size_t)idx * K2_];
    }

    int lz = 0;      // sum of power-of-two exponents (exact)
    SUBBAR();

#define STEP(EI, SRC, DST, DOREN, TCUR) do {                                  \
    const float E_ = __expf(eraw[EI]);                                        \
    const ulonglong2* Vp_ = reinterpret_cast<const ulonglong2*>(vb[half][SRC]); \
    ulonglong2 vv0_ = Vp_[0];                                                 \
    unsigned long long a0_=0ULL, a1_=0ULL, a2_=0ULL, a3_=0ULL;                \
    float scale_;                                                             \
    if (DOREN) {                                                              \
        unsigned bits_ = (unsigned)(vv0_.x & 0xffffffffULL);                  \
        int e_ = 0;                                                           \
        if (bits_) {                                                          \
            e_ = (int)((bits_ >> 23) & 0xff) - 127;                           \
            e_ = max(-126, min(126, e_));                                     \
        }                                                                     \
        lz += e_;                                                             \
        scale_ = __uint_as_float((unsigned)(127 - e_) << 23) * E_;            \
    } else {                                                                  \
        scale_ = E_;                                                          \
    }                                                                         \
    FFMA2(a0_, m2[0], vv0_.x, a0_);                                           \
    FFMA2(a1_, m2[1], vv0_.y, a1_);                                           \
    _Pragma("unroll")                                                         \
    for (int j_ = 1; j_ < 13; ++j_) {                                         \
        ulonglong2 vv_ = Vp_[j_];                                             \
        if (j_ & 1) { FFMA2(a2_, m2[2*j_], vv_.x, a2_);                       \
                      FFMA2(a3_, m2[2*j_+1], vv_.y, a3_); }                   \
        else        { FFMA2(a0_, m2[2*j_], vv_.x, a0_);                       \
                      FFMA2(a1_, m2[2*j_+1], vv_.y, a1_); }                   \
    }                                                                         \
    FADD2(a0_, a0_, a2_);                                                     \
    FADD2(a1_, a1_, a3_);                                                     \
    FADD2(a0_, a0_, a1_);                                                     \
    float qlo_ = __uint_as_float((unsigned)(a0_ & 0xffffffffULL));            \
    float qhi_ = __uint_as_float((unsigned)(a0_ >> 32));                      \
    if (s < K2_) vb[half][DST][s] = (qlo_ + qhi_) * scale_;                   \
    { int idx_ = (TCUR) + 8; idx_ = (idx_ > len - 1) ? (len - 1) : idx_;      \
      eraw[EI] = eb[(size_t)idx_ * K2_]; }                                    \
    SUBBAR();                                                                 \
} while (0)

    int t = 0;
    const int nmain = len & ~7;
    for (; t < nmain; t += 8) {
        STEP(0, 0, 1, true,  t + 0);
        STEP(1, 1, 0, false, t + 1);
        STEP(2, 0, 1, true,  t + 2);
        STEP(3, 1, 0, false, t + 3);
        STEP(4, 0, 1, true,  t + 4);
        STEP(5, 1, 0, false, t + 5);
        STEP(6, 0, 1, true,  t + 6);
        STEP(7, 1, 0, false, t + 7);
    }
    // tail (0..7 steps), static ring slots since nmain % 8 == 0
    if (t < len) { STEP(0, 0, 1, true, t); ++t; }
    if (t < len) { STEP(1, 1, 0, true, t); ++t; }
    if (t < len) { STEP(2, 0, 1, true, t); ++t; }
    if (t < len) { STEP(3, 1, 0, true, t); ++t; }
    if (t < len) { STEP(4, 0, 1, true, t); ++t; }
    if (t < len) { STEP(5, 1, 0, true, t); ++t; }
    if (t < len) { STEP(6, 0, 1, true, t); ++t; }
#undef STEP

    // final state lives in vb[half][len & 1]
    const float* vf = vb[half][len & 1];

    // terminal: fw = lz*ln2 + log( sum_s exp(trans[STOP][s]) * v[s] )
    float term = 0.0f;
    if (s < K2_) term = __expf(tr[(K2_ - 1) * K2_ + s]) * vf[s];
    red[half][s] = term;
    SUBBAR();
    if (s == 0) {
        float acc = 0.0f;
        for (int i = 0; i < K2_; ++i) acc += red[half][i];
        g_fw[b] = (float)((double)lz * 0.69314718055994530942) + __logf(acc);
    }
#undef SUBBAR
}

// ---------------------------------------------------------------------------
// Gold score: one batch per 256-thread block.
// ---------------------------------------------------------------------------
__global__ void gold_kernel(const float* __restrict__ em,
                            const float* __restrict__ tr,
                            const void* __restrict__ labs_raw)
{
    const int b = blockIdx.x;
    const int tid = threadIdx.x;
    const int len = g_len[b];
    const int is64 = g_i64;
    const long long* lb64 = ((const long long*)labs_raw) + (size_t)b * T_;
    const int*       lb32 = ((const int*)labs_raw) + (size_t)b * T_;

    float acc = 0.0f;
    for (int t = tid; t < len; t += 256) {
        int lab  = is64 ? (int)lb64[t] : lb32[t];
        acc += em[((size_t)b * T_ + t) * K2_ + lab];
        int prev = (t == 0) ? (K2_ - 2)
                            : (is64 ? (int)lb64[t - 1] : lb32[t - 1]);
        acc += tr[lab * K2_ + prev];
    }

    __shared__ float sm[256];
    sm[tid] = acc;
    __syncthreads();
    for (int off = 128; off > 0; off >>= 1) {
        if (tid < off) sm[tid] += sm[tid + off];
        __syncthreads();
    }
    if (tid == 0) {
        int lastlab = is64 ? (int)lb64[len - 1] : lb32[len - 1];
        float gold = sm[0] + tr[(K2_ - 1) * K2_ + lastlab];
        g_diff[b] = g_fw[b] - gold;
    }
}

// ---------------------------------------------------------------------------
// Deterministic final mean over 256 batches.
// ---------------------------------------------------------------------------
__global__ void reduce_kernel(float* __restrict__ out)
{
    const int tid = threadIdx.x;
    __shared__ float sm[256];
    sm[tid] = g_diff[tid];
    __syncthreads();
    for (int off = 128; off > 0; off >>= 1) {
        if (tid < off) sm[tid] += sm[tid + off];
        __syncthreads();
    }
    if (tid == 0) out[0] = sm[0] * (1.0f / 256.0f);
}

extern "C" void kernel_launch(void* const* d_in, const int* in_sizes, int n_in,
                              void* d_out, int out_size)
{
    const float* em   = (const float*)d_in[0];   // [B, T, K2] f32
    const float* tr   = (const float*)d_in[1];   // [K2, K2]   f32
    const void*  lens = d_in[2];                 // [B]    i32 or i64
    const void*  labs = d_in[3];                 // [B, T] i32 or i64

    prep_kernel<<<1, 256>>>(lens);
    fwd_kernel<<<B_ / 2, 128>>>(em, tr);
    gold_kernel<<<B_, 256>>>(em, tr, labs);
    reduce_kernel<<<1, 256>>>((float*)d_out);
}